// round 8
// baseline (speedup 1.0000x reference)
#include <cuda_runtime.h>
#include <cuda_bf16.h>

// Problem constants
#define F 26
#define B 16384
#define V 100000
#define D 32
#define H 13

#define TPB    256
#define GRID   1184                 // 148 SMs x 8 resident blocks = single balanced wave
#define ITEMS  12
#define STRIDE (GRID * TPB)         // 303,104 float4s; % 8 == 0 -> d4 constant per thread
#define TOTAL  (B * F * (D / 4))    // 3,407,872 float4s
// items 0..10 always valid (11*STRIDE + max p0 < TOTAL); item 11 valid for first 288 blocks

// Fused kernel:
//   prologue (warp 0): scale[f] = sigmoid(w2 @ relu(w1 @ mean_d(emb[f, x[f,B-1], :])))
//     (reference uses ONLY the last batch row for the gate: scale = gate[-1])
//   main: out[b, f*D+d] = tables[f][x[f,b]][d] * scale[f]
// Grid-stride item layout, one float4 per item. 8 consecutive threads share one
// (b,f) row -> coalesced gather lines; stores linear per item-slice.
__global__ void __launch_bounds__(TPB, 8) fused_gather_se_kernel(
    const int* __restrict__ x,
    const float* __restrict__ tables,
    const float* __restrict__ w1,
    const float* __restrict__ w2,
    float* __restrict__ out) {

    __shared__ float s_sein[F];
    __shared__ float s_h[H];
    __shared__ float s_scale[F];

    const int t = threadIdx.x;

    // ---- SE-gate prologue: warp 0 only, redundant per block (L2-hot) ----
    if (t < 32) {
        if (t < F) {
            int idx = __ldg(&x[t * B + (B - 1)]);
            const float4* row = reinterpret_cast<const float4*>(
                tables + (size_t)t * ((size_t)V * D) + (size_t)idx * D);
            float s = 0.f;
            #pragma unroll
            for (int i = 0; i < D / 4; i++) {
                float4 v = __ldg(&row[i]);
                s += (v.x + v.y) + (v.z + v.w);
            }
            s_sein[t] = s * (1.0f / (float)D);
        }
        __syncwarp();
        if (t < H) {
            float acc = 0.f;
            #pragma unroll
            for (int f = 0; f < F; f++) acc += w1[t * F + f] * s_sein[f];
            s_h[t] = fmaxf(acc, 0.f);
        }
        __syncwarp();
        if (t < F) {
            float acc = 0.f;
            #pragma unroll
            for (int j = 0; j < H; j++) acc += w2[t * H + j] * s_h[j];
            s_scale[t] = 1.0f / (1.0f + __expf(-acc));
        }
    }

    // ---- index loads + gather offsets for all 12 items (batched -> high MLP) ----
    const int p0       = blockIdx.x * TPB + t;
    const unsigned dby = (unsigned)(p0 & 7) * 16u;  // byte offset of float4 within row
    const bool v11     = (p0 + 11 * STRIDE) < TOTAL;

    unsigned off[ITEMS];   // 32-bit byte offsets into tables (span 333MB < 4GB)
    #pragma unroll
    for (int i = 0; i < ITEMS; i++) {
        if (i < 11 || v11) {
            int p = p0 + i * STRIDE;
            int r = p >> 3;
            int f = r % F;
            int b = r / F;
            int idx = __ldg(&x[f * B + b]);
            off[i] = (unsigned)(f * V + idx) * (unsigned)(D * 4) + dby;
        } else {
            off[i] = 0;
        }
    }

    const char*   tb   = reinterpret_cast<const char*>(tables);
    float4* __restrict__ o4 = reinterpret_cast<float4*>(out);

    float4 v[4];

    // group 0: issue gathers BEFORE the barrier (overlaps prologue latency)
    #pragma unroll
    for (int j = 0; j < 4; j++)
        v[j] = __ldg(reinterpret_cast<const float4*>(tb + off[j]));

    __syncthreads();   // s_scale ready; group-0 gathers already in flight

    // group 0 store
    #pragma unroll
    for (int j = 0; j < 4; j++) {
        int p = p0 + j * STRIDE;
        float s = s_scale[(p >> 3) % F];
        v[j].x *= s; v[j].y *= s; v[j].z *= s; v[j].w *= s;
        __stcs(&o4[p], v[j]);   // streaming: output never re-read; keep tables in L2
    }

    // group 1
    #pragma unroll
    for (int j = 0; j < 4; j++)
        v[j] = __ldg(reinterpret_cast<const float4*>(tb + off[4 + j]));
    #pragma unroll
    for (int j = 0; j < 4; j++) {
        int p = p0 + (4 + j) * STRIDE;
        float s = s_scale[(p >> 3) % F];
        v[j].x *= s; v[j].y *= s; v[j].z *= s; v[j].w *= s;
        __stcs(&o4[p], v[j]);
    }

    // group 2 (item 11 predicated)
    #pragma unroll
    for (int j = 0; j < 4; j++) {
        if (j < 3 || v11)
            v[j] = __ldg(reinterpret_cast<const float4*>(tb + off[8 + j]));
    }
    #pragma unroll
    for (int j = 0; j < 4; j++) {
        if (j < 3 || v11) {
            int p = p0 + (8 + j) * STRIDE;
            float s = s_scale[(p >> 3) % F];
            v[j].x *= s; v[j].y *= s; v[j].z *= s; v[j].w *= s;
            __stcs(&o4[p], v[j]);
        }
    }
}

extern "C" void kernel_launch(void* const* d_in, const int* in_sizes, int n_in,
                              void* d_out, int out_size) {
    const int*   x      = (const int*)d_in[0];
    const float* tables = (const float*)d_in[1];
    const float* w1     = (const float*)d_in[2];
    const float* w2     = (const float*)d_in[3];
    float*       out    = (float*)d_out;

    fused_gather_se_kernel<<<GRID, TPB>>>(x, tables, w1, w2, out);
}

// round 13
// speedup vs baseline: 1.0964x; 1.0964x over previous
#include <cuda_runtime.h>
#include <cuda_bf16.h>

// Problem constants
#define F 26
#define B 16384
#define V 100000
#define D 32
#define H 13

#define TPB   128
#define ITEMS 8
// total float4s = B*F*(D/4) = 3,407,872 = 3328 blocks * 128 threads * 8 items
#define GRID  3328

// Fused kernel:
//   prologue (warp 0): scale[f] = sigmoid(w2 @ relu(w1 @ mean_d(emb[f, x[f,B-1], :])))
//     (reference uses ONLY the last batch row for the gate: scale = gate[-1])
//   main: out[b, f*D+d] = tables[f][x[f,b]][d] * scale[f]
// One thread per 8 output float4s, item stride = TPB (128 % 8 == 0 -> the
// float4-within-row offset d4 is constant per thread). 8 consecutive threads
// share one (b,f) row -> coalesced gather lines; stores are linear.
__global__ void __launch_bounds__(TPB, 16) fused_gather_se_kernel(
    const int* __restrict__ x,
    const float* __restrict__ tables,
    const float* __restrict__ w1,
    const float* __restrict__ w2,
    float* __restrict__ out) {

    __shared__ float s_sein[F];
    __shared__ float s_h[H];
    __shared__ float s_scale[F];

    const int t = threadIdx.x;

    // ---- SE-gate prologue: warp 0 only (rows L2-hot after first blocks) ----
    if (t < 32) {
        if (t < F) {
            int idx = __ldg(&x[t * B + (B - 1)]);
            const float4* row = reinterpret_cast<const float4*>(
                tables + (size_t)t * ((size_t)V * D) + (size_t)idx * D);
            float s = 0.f;
            #pragma unroll
            for (int i = 0; i < D / 4; i++) {
                float4 v = __ldg(&row[i]);
                s += (v.x + v.y) + (v.z + v.w);
            }
            s_sein[t] = s * (1.0f / (float)D);
        }
        __syncwarp();
        if (t < H) {
            float acc = 0.f;
            #pragma unroll
            for (int f = 0; f < F; f++) acc += w1[t * F + f] * s_sein[f];
            s_h[t] = fmaxf(acc, 0.f);
        }
        __syncwarp();
        if (t < F) {
            float acc = 0.f;
            #pragma unroll
            for (int j = 0; j < H; j++) acc += w2[t * H + j] * s_h[j];
            s_scale[t] = 1.0f / (1.0f + __expf(-acc));
        }
    }

    // ---- main gather-scale-store, 8 float4s per thread, contiguous slab ----
    const int base     = blockIdx.x * (TPB * ITEMS) + t;
    const unsigned dby = (unsigned)(base & 7) * 16u;  // const per thread
    const int r0       = base >> 3;                   // row of item 0; +16 rows/item

    // Batch the 8 index loads -> 32-bit byte offsets (table span 333MB < 4GB)
    unsigned off[ITEMS];
    #pragma unroll
    for (int i = 0; i < ITEMS; i++) {
        int r = r0 + i * (TPB / 8);
        int f = r % F;
        int b = r / F;
        int idx = __ldg(&x[f * B + b]);
        off[i] = (unsigned)(f * V + idx) * (unsigned)(D * 4) + dby;
    }

    const char* tb = reinterpret_cast<const char*>(tables);
    float4* __restrict__ o4 = reinterpret_cast<float4*>(out);

    float4 v[4];

    // group 0 gathers issued BEFORE the barrier: overlap prologue latency
    #pragma unroll
    for (int j = 0; j < 4; j++)
        v[j] = __ldg(reinterpret_cast<const float4*>(tb + off[j]));

    __syncthreads();   // s_scale ready; group-0 gathers already in flight

    #pragma unroll
    for (int j = 0; j < 4; j++) {
        float s = s_scale[(r0 + j * (TPB / 8)) % F];
        v[j].x *= s; v[j].y *= s; v[j].z *= s; v[j].w *= s;
        // streaming store: output never re-read; keep table rows in L2
        __stcs(&o4[base + j * TPB], v[j]);
    }

    // group 1
    #pragma unroll
    for (int j = 0; j < 4; j++)
        v[j] = __ldg(reinterpret_cast<const float4*>(tb + off[4 + j]));
    #pragma unroll
    for (int j = 0; j < 4; j++) {
        float s = s_scale[(r0 + (4 + j) * (TPB / 8)) % F];
        v[j].x *= s; v[j].y *= s; v[j].z *= s; v[j].w *= s;
        __stcs(&o4[base + (4 + j) * TPB], v[j]);
    }
}

extern "C" void kernel_launch(void* const* d_in, const int* in_sizes, int n_in,
                              void* d_out, int out_size) {
    const int*   x      = (const int*)d_in[0];
    const float* tables = (const float*)d_in[1];
    const float* w1     = (const float*)d_in[2];
    const float* w2     = (const float*)d_in[3];
    float*       out    = (float*)d_out;

    fused_gather_se_kernel<<<GRID, TPB>>>(x, tables, w1, w2, out);
}